// round 1
// baseline (speedup 1.0000x reference)
#include <cuda_runtime.h>

// Problem constants
#define Bx 2048
#define Tt 512
#define Dd 6
#define Hh 40
#define Gg 160   // 4*H

#define NWARP 4          // warps per CTA
#define NB 4             // batch elements per warp
#define BPC (NWARP*NB)   // 16 batch per CTA
#define NCTA (Bx/BPC)    // 128 CTAs

// Shared memory layout (in floats)
#define OFF_WI0 0
#define OFF_WH0 (OFF_WI0 + Dd*Gg)        //   960
#define OFF_WI1 (OFF_WH0 + Hh*Gg)        //  7360
#define OFF_WH1 (OFF_WI1 + Hh*Gg)        // 13760
#define OFF_WI2 (OFF_WH1 + Hh*Gg)        // 20160
#define OFF_WH2 (OFF_WI2 + Hh*Gg)        // 26560
#define OFF_B0  (OFF_WH2 + Hh*Gg)        // 32960
#define OFF_B1  (OFF_B0 + Gg)
#define OFF_B2  (OFF_B1 + Gg)
#define OFF_WOUT (OFF_B2 + Gg)           // 33440
#define OFF_H0  (OFF_WOUT + Hh)          // 33480
#define OFF_H1  (OFF_H0 + BPC*Hh)
#define OFF_H2  (OFF_H1 + BPC*Hh)
#define OFF_C0  (OFF_H2 + BPC*Hh)
#define OFF_C1  (OFF_C0 + BPC*Hh)
#define OFF_C2  (OFF_C1 + BPC*Hh)
#define OFF_GT  (OFF_C2 + BPC*Hh)        // 37320
#define OFF_XS  (OFF_GT + BPC*Gg)        // 39880
#define SMEM_FLOATS (OFF_XS + BPC*Dd)    // 39976 floats = 159904 B

__device__ __forceinline__ float sigmoidf_(float x) {
    return __fdividef(1.0f, 1.0f + __expf(-x));
}
__device__ __forceinline__ float tanhf_(float x) {
    return __fdividef(2.0f, 1.0f + __expf(-2.0f * x)) - 1.0f;
}

// Accumulate gates: acc[m][b] += sum_k WT[k*160 + lane+32m] * hin[b*stride + k]
// WT layout is transposed (k-major) -> lane-consecutive => conflict-free LDS.
// hin reads are warp-broadcast (same address all lanes).
template<int K>
__device__ __forceinline__ void accum(float acc[5][NB], const float* __restrict__ WT,
                                      const float* __restrict__ hin, int stride, int lane)
{
#pragma unroll 8
    for (int k = 0; k < K; k++) {
        const float* wp = WT + k * Gg + lane;
        float w0 = wp[0];
        float w1 = wp[32];
        float w2 = wp[64];
        float w3 = wp[96];
        float w4 = wp[128];
#pragma unroll
        for (int b = 0; b < NB; b++) {
            float hv = hin[b * stride + k];
            acc[0][b] = fmaf(w0, hv, acc[0][b]);
            acc[1][b] = fmaf(w1, hv, acc[1][b]);
            acc[2][b] = fmaf(w2, hv, acc[2][b]);
            acc[3][b] = fmaf(w3, hv, acc[3][b]);
            acc[4][b] = fmaf(w4, hv, acc[4][b]);
        }
    }
}

__device__ __forceinline__ void init_bias(float acc[5][NB], const float* __restrict__ bias, int lane)
{
    float b0v = bias[lane];
    float b1v = bias[lane + 32];
    float b2v = bias[lane + 64];
    float b3v = bias[lane + 96];
    float b4v = bias[lane + 128];
#pragma unroll
    for (int b = 0; b < NB; b++) {
        acc[0][b] = b0v; acc[1][b] = b1v; acc[2][b] = b2v;
        acc[3][b] = b3v; acc[4][b] = b4v;
    }
}

__device__ __forceinline__ void store_gates(const float acc[5][NB], float* __restrict__ gsm, int lane)
{
#pragma unroll
    for (int m = 0; m < 5; m++)
#pragma unroll
        for (int b = 0; b < NB; b++)
            gsm[b * Gg + lane + 32 * m] = acc[m][b];
}

// h/c update for the warp's NB*H units (gate order i,f,g,o)
__device__ __forceinline__ void update_hc(const float* __restrict__ gsm,
                                          float* __restrict__ hsm,
                                          float* __restrict__ csm, int lane)
{
#pragma unroll
    for (int r = 0; r < 5; r++) {            // NB*H / 32 = 160/32 = 5
        int idx = lane + 32 * r;             // 0..159
        int b = idx / Hh;
        int u = idx - b * Hh;
        float gi = gsm[b * Gg + u];
        float gf = gsm[b * Gg + 40 + u];
        float gg = gsm[b * Gg + 80 + u];
        float go = gsm[b * Gg + 120 + u];
        float iv = sigmoidf_(gi);
        float fv = sigmoidf_(gf);
        float gv = tanhf_(gg);
        float ov = sigmoidf_(go);
        float c = fmaf(fv, csm[b * Hh + u], iv * gv);
        csm[b * Hh + u] = c;
        hsm[b * Hh + u] = ov * tanhf_(c);
    }
}

extern __shared__ float sm[];

__global__ void __launch_bounds__(NWARP * 32, 1)
lstm_fused_kernel(const float* __restrict__ x,
                  const float* __restrict__ Wih0, const float* __restrict__ Whh0,
                  const float* __restrict__ bih0, const float* __restrict__ bhh0,
                  const float* __restrict__ Wih1, const float* __restrict__ Whh1,
                  const float* __restrict__ bih1, const float* __restrict__ bhh1,
                  const float* __restrict__ Wih2, const float* __restrict__ Whh2,
                  const float* __restrict__ bih2, const float* __restrict__ bhh2,
                  const float* __restrict__ Wout, const float* __restrict__ bout,
                  float* __restrict__ out)
{
    const int tid = threadIdx.x;

    // ---- Load weights into shared, transposed: WT[k*G + j] = W[j*K + k] ----
    {
        auto loadT = [&](const float* __restrict__ src, float* __restrict__ dst, int K) {
            for (int idx = tid; idx < Gg * K; idx += NWARP * 32) {
                int j = idx / K;
                int k = idx - j * K;
                dst[k * Gg + j] = src[idx];
            }
        };
        loadT(Wih0, sm + OFF_WI0, Dd);
        loadT(Whh0, sm + OFF_WH0, Hh);
        loadT(Wih1, sm + OFF_WI1, Hh);
        loadT(Whh1, sm + OFF_WH1, Hh);
        loadT(Wih2, sm + OFF_WI2, Hh);
        loadT(Whh2, sm + OFF_WH2, Hh);
        for (int idx = tid; idx < Gg; idx += NWARP * 32) {
            sm[OFF_B0 + idx] = bih0[idx] + bhh0[idx];
            sm[OFF_B1 + idx] = bih1[idx] + bhh1[idx];
            sm[OFF_B2 + idx] = bih2[idx] + bhh2[idx];
        }
        if (tid < Hh) sm[OFF_WOUT + tid] = Wout[tid];
        // zero h/c state (H0..C2 are contiguous)
        for (int idx = tid; idx < 6 * BPC * Hh; idx += NWARP * 32)
            sm[OFF_H0 + idx] = 0.0f;
    }
    __syncthreads();

    const int warp = tid >> 5;
    const int lane = tid & 31;
    const int bw = warp * NB;                         // batch offset inside CTA
    const int bglob = blockIdx.x * BPC + bw;          // global batch base for this warp

    float* gsm = sm + OFF_GT + bw * Gg;
    float* xs  = sm + OFF_XS + bw * Dd;
    float* h0  = sm + OFF_H0 + bw * Hh;
    float* h1  = sm + OFF_H1 + bw * Hh;
    float* h2  = sm + OFF_H2 + bw * Hh;
    float* c0  = sm + OFF_C0 + bw * Hh;
    float* c1  = sm + OFF_C1 + bw * Hh;
    float* c2  = sm + OFF_C2 + bw * Hh;

    const float boutv = bout[0];

    // x streaming: lanes 0..23 each own one (b,k) of the warp's [NB][D] slab.
    const int bb = lane / Dd;                 // 0..5 (only <NB used)
    const int kk = lane - bb * Dd;
    const int bbc = (bb < NB) ? bb : (NB - 1);  // clamp to stay in-bounds
    const float* xptr = x + ((size_t)(bglob + bbc) * Tt) * Dd + kk;
    float xr = xptr[0];                        // x at t=0

    const int ob = lane >> 3;                  // output reduction: b = lane/8
    const int sub = lane & 7;

    for (int t = 0; t < Tt; t++) {
        // stage x_t into shared, prefetch x_{t+1}
        if (lane < NB * Dd) xs[bb * Dd + kk] = xr;
        __syncwarp();
        {
            int tn = (t + 1 < Tt) ? (t + 1) : t;
            xr = xptr[tn * Dd];
        }

        float acc[5][NB];

        // ---- Layer 0: gates = Wih0@x_t + Whh0@h0 + bias ----
        init_bias(acc, sm + OFF_B0, lane);
        accum<Dd>(acc, sm + OFF_WI0, xs, Dd, lane);
        accum<Hh>(acc, sm + OFF_WH0, h0, Hh, lane);
        store_gates(acc, gsm, lane);
        __syncwarp();
        update_hc(gsm, h0, c0, lane);
        __syncwarp();

        // ---- Layer 1: gates = Wih1@h0 + Whh1@h1 + bias ----
        init_bias(acc, sm + OFF_B1, lane);
        accum<Hh>(acc, sm + OFF_WI1, h0, Hh, lane);
        accum<Hh>(acc, sm + OFF_WH1, h1, Hh, lane);
        store_gates(acc, gsm, lane);
        __syncwarp();
        update_hc(gsm, h1, c1, lane);
        __syncwarp();

        // ---- Layer 2: gates = Wih2@h1 + Whh2@h2 + bias ----
        init_bias(acc, sm + OFF_B2, lane);
        accum<Hh>(acc, sm + OFF_WI2, h1, Hh, lane);
        accum<Hh>(acc, sm + OFF_WH2, h2, Hh, lane);
        store_gates(acc, gsm, lane);
        __syncwarp();
        update_hc(gsm, h2, c2, lane);
        __syncwarp();

        // ---- Output projection: out[b,t] = dot(Wout, h2[b]) + bout ----
        float s = 0.0f;
#pragma unroll
        for (int q = 0; q < 5; q++) {
            int u = sub * 5 + q;
            s = fmaf(sm[OFF_WOUT + u], h2[ob * Hh + u], s);
        }
        s += __shfl_down_sync(0xffffffffu, s, 4, 8);
        s += __shfl_down_sync(0xffffffffu, s, 2, 8);
        s += __shfl_down_sync(0xffffffffu, s, 1, 8);
        if (sub == 0) out[(size_t)(bglob + ob) * Tt + t] = s + boutv;
        __syncwarp();
    }
}

extern "C" void kernel_launch(void* const* d_in, const int* in_sizes, int n_in,
                              void* d_out, int out_size)
{
    const float* x    = (const float*)d_in[0];
    const float* Wih0 = (const float*)d_in[1];
    const float* Whh0 = (const float*)d_in[2];
    const float* bih0 = (const float*)d_in[3];
    const float* bhh0 = (const float*)d_in[4];
    const float* Wih1 = (const float*)d_in[5];
    const float* Whh1 = (const float*)d_in[6];
    const float* bih1 = (const float*)d_in[7];
    const float* bhh1 = (const float*)d_in[8];
    const float* Wih2 = (const float*)d_in[9];
    const float* Whh2 = (const float*)d_in[10];
    const float* bih2 = (const float*)d_in[11];
    const float* bhh2 = (const float*)d_in[12];
    const float* Wout = (const float*)d_in[13];
    const float* bout = (const float*)d_in[14];
    float* out = (float*)d_out;

    (void)in_sizes; (void)n_in; (void)out_size;

    cudaFuncSetAttribute(lstm_fused_kernel,
                         cudaFuncAttributeMaxDynamicSharedMemorySize,
                         SMEM_FLOATS * (int)sizeof(float));

    lstm_fused_kernel<<<NCTA, NWARP * 32, SMEM_FLOATS * sizeof(float)>>>(
        x, Wih0, Whh0, bih0, bhh0, Wih1, Whh1, bih1, bhh1,
        Wih2, Whh2, bih2, bhh2, Wout, bout, out);
}